// round 1
// baseline (speedup 1.0000x reference)
#include <cuda_runtime.h>
#include <math.h>

// Problem constants (fixed by the reference: B=4, T=4096, D=1024)
#define Bn 4
#define Tn 4096
#define Dn 1024
#define Mn (Bn * Tn)   // 16384 rows

// ---- Device scratch (allocation-free rule: __device__ globals) ----
// Pre-scaled weights: W'[i][e][d] = W_i[e][d] * time_mix_i[d], i in {k,v,r}
__device__ float g_W[3u * Dn * Dn];       // 12 MB
// Per-output-column bias: b_i[e] = sum_d W_i[e][d] * last_x[d] * (1 - tm_i[d])
__device__ float g_b[3 * Dn];
// Intermediate rwkv = sigmoid(r) * wkv, [M, D]
__device__ float g_rwkv[(size_t)Mn * Dn]; // 64 MB

// ---------------------------------------------------------------------------
// Prep 1: scale the three weight matrices by their time-mix vectors (columns)
// ---------------------------------------------------------------------------
__global__ void prep_scale(const float* __restrict__ Wk,
                           const float* __restrict__ Wv,
                           const float* __restrict__ Wr,
                           const float* __restrict__ tmk,
                           const float* __restrict__ tmv,
                           const float* __restrict__ tmr) {
    int idx = blockIdx.x * blockDim.x + threadIdx.x;   // over D*D/4 float4s
    if (idx >= Dn * Dn / 4) return;
    int base = idx * 4;
    int d = base & (Dn - 1);                            // column index (mod D)
    float4 k4 = *(const float4*)&Wk[base];
    float4 v4 = *(const float4*)&Wv[base];
    float4 r4 = *(const float4*)&Wr[base];
    float4 mk = *(const float4*)&tmk[d];
    float4 mv = *(const float4*)&tmv[d];
    float4 mr = *(const float4*)&tmr[d];
    float4 ok = make_float4(k4.x * mk.x, k4.y * mk.y, k4.z * mk.z, k4.w * mk.w);
    float4 ov = make_float4(v4.x * mv.x, v4.y * mv.y, v4.z * mv.z, v4.w * mv.w);
    float4 orr = make_float4(r4.x * mr.x, r4.y * mr.y, r4.z * mr.z, r4.w * mr.w);
    *(float4*)&g_W[0u * Dn * Dn + base] = ok;
    *(float4*)&g_W[1u * Dn * Dn + base] = ov;
    *(float4*)&g_W[2u * Dn * Dn + base] = orr;
}

// ---------------------------------------------------------------------------
// Prep 2: biases b_i[e] = sum_d W_i[e][d] * last_x[d] * (1 - tm_i[d])
// (last_x is the zero state in the dataset, but we compute it generally)
// ---------------------------------------------------------------------------
__global__ void prep_bias(const float* __restrict__ Wk,
                          const float* __restrict__ Wv,
                          const float* __restrict__ Wr,
                          const float* __restrict__ lx,
                          const float* __restrict__ tmk,
                          const float* __restrict__ tmv,
                          const float* __restrict__ tmr) {
    __shared__ float red[256];
    int e = blockIdx.x;
    int t = threadIdx.x;
    const float* Ws[3] = {Wk, Wv, Wr};
    const float* tms[3] = {tmk, tmv, tmr};
#pragma unroll
    for (int i = 0; i < 3; i++) {
        float s = 0.f;
        for (int d = t; d < Dn; d += 256)
            s += Ws[i][(size_t)e * Dn + d] * lx[d] * (1.f - tms[i][d]);
        red[t] = s;
        __syncthreads();
        for (int off = 128; off > 0; off >>= 1) {
            if (t < off) red[t] += red[t + off];
            __syncthreads();
        }
        if (t == 0) g_b[i * Dn + e] = red[0];
        __syncthreads();
    }
}

// ---------------------------------------------------------------------------
// GEMM 1 (fused k/v/r + WKV epilogue):
//   acc_i[m][e] = sum_d x[m][d] * g_W[i][e][d]     (3 accumulators)
//   k = acc0+b0, v = acc1+b1, r = acc2+b2
//   rwkv = sigmoid(r) * (last_num[e] + exp(tf[e]+k)*v) / (last_den[e] + exp(tf[e]+k))
//   at t==T-1 also emit num/den state outputs.
// 64x64 tile, BK=16, 256 threads, 4x4 per thread, 3 accumulator sets.
// ---------------------------------------------------------------------------
__global__ __launch_bounds__(256) void gemm_kvr(
    const float* __restrict__ x,
    const float* __restrict__ tf,
    const float* __restrict__ td,
    const float* __restrict__ lnum,
    const float* __restrict__ lden,
    float* __restrict__ out_num,
    float* __restrict__ out_den) {
    __shared__ float As[16][68];
    __shared__ float Bs[3][16][68];

    const int t = threadIdx.x;
    const int e0 = blockIdx.x * 64;
    const int m0 = blockIdx.y * 64;
    const int lrow = t >> 2;      // 0..63
    const int lq = t & 3;         // 0..3 (which float4 of the 16-wide k slab)
    const int ty = t >> 4;        // 0..15 -> row group
    const int tx = t & 15;        // 0..15 -> col group

    float acc[3][4][4];
#pragma unroll
    for (int i = 0; i < 3; i++)
#pragma unroll
        for (int a = 0; a < 4; a++)
#pragma unroll
            for (int b = 0; b < 4; b++) acc[i][a][b] = 0.f;

    for (int kb = 0; kb < Dn; kb += 16) {
        float4 a4 = *(const float4*)&x[(size_t)(m0 + lrow) * Dn + kb + lq * 4];
        As[lq * 4 + 0][lrow] = a4.x;
        As[lq * 4 + 1][lrow] = a4.y;
        As[lq * 4 + 2][lrow] = a4.z;
        As[lq * 4 + 3][lrow] = a4.w;
#pragma unroll
        for (int i = 0; i < 3; i++) {
            float4 b4 = *(const float4*)&g_W[(size_t)i * Dn * Dn +
                                             (size_t)(e0 + lrow) * Dn + kb + lq * 4];
            Bs[i][lq * 4 + 0][lrow] = b4.x;
            Bs[i][lq * 4 + 1][lrow] = b4.y;
            Bs[i][lq * 4 + 2][lrow] = b4.z;
            Bs[i][lq * 4 + 3][lrow] = b4.w;
        }
        __syncthreads();
#pragma unroll
        for (int kk = 0; kk < 16; kk++) {
            float a[4], bk[4], bv[4], br[4];
#pragma unroll
            for (int u = 0; u < 4; u++) a[u] = As[kk][ty * 4 + u];
#pragma unroll
            for (int u = 0; u < 4; u++) bk[u] = Bs[0][kk][tx * 4 + u];
#pragma unroll
            for (int u = 0; u < 4; u++) bv[u] = Bs[1][kk][tx * 4 + u];
#pragma unroll
            for (int u = 0; u < 4; u++) br[u] = Bs[2][kk][tx * 4 + u];
#pragma unroll
            for (int i = 0; i < 4; i++)
#pragma unroll
                for (int j = 0; j < 4; j++) {
                    acc[0][i][j] = fmaf(a[i], bk[j], acc[0][i][j]);
                    acc[1][i][j] = fmaf(a[i], bv[j], acc[1][i][j]);
                    acc[2][i][j] = fmaf(a[i], br[j], acc[2][i][j]);
                }
        }
        __syncthreads();
    }

    // Epilogue: WKV numerics
#pragma unroll
    for (int i = 0; i < 4; i++) {
        int m = m0 + ty * 4 + i;
#pragma unroll
        for (int j = 0; j < 4; j++) {
            int e = e0 + tx * 4 + j;
            float kv = acc[0][i][j] + g_b[0 * Dn + e];
            float vv = acc[1][i][j] + g_b[1 * Dn + e];
            float rv = acc[2][i][j] + g_b[2 * Dn + e];
            float efk = expf(tf[e] + kv);
            float wkv = (lnum[e] + efk * vv) / (lden[e] + efk);
            float sig = 1.f / (1.f + expf(-rv));
            g_rwkv[(size_t)m * Dn + e] = sig * wkv;
            if ((m & (Tn - 1)) == Tn - 1) {  // t == T-1 -> state outputs
                int bidx = m / Tn;
                float ek = expf(kv);
                float dec = expf(-expf(td[e]));
                out_num[bidx * Dn + e] = dec * lnum[e] + ek * vv;
                out_den[bidx * Dn + e] = dec * lden[e] + ek;
            }
        }
    }
}

// ---------------------------------------------------------------------------
// GEMM 2: out[m][e] = sum_d rwkv[m][d] * Wo[e][d]
// ---------------------------------------------------------------------------
__global__ __launch_bounds__(256) void gemm_out(const float* __restrict__ Wo,
                                                float* __restrict__ out) {
    __shared__ float As[16][68];
    __shared__ float Bs[16][68];

    const int t = threadIdx.x;
    const int e0 = blockIdx.x * 64;
    const int m0 = blockIdx.y * 64;
    const int lrow = t >> 2;
    const int lq = t & 3;
    const int ty = t >> 4;
    const int tx = t & 15;

    float acc[4][4];
#pragma unroll
    for (int a = 0; a < 4; a++)
#pragma unroll
        for (int b = 0; b < 4; b++) acc[a][b] = 0.f;

    for (int kb = 0; kb < Dn; kb += 16) {
        float4 a4 = *(const float4*)&g_rwkv[(size_t)(m0 + lrow) * Dn + kb + lq * 4];
        As[lq * 4 + 0][lrow] = a4.x;
        As[lq * 4 + 1][lrow] = a4.y;
        As[lq * 4 + 2][lrow] = a4.z;
        As[lq * 4 + 3][lrow] = a4.w;
        float4 b4 = *(const float4*)&Wo[(size_t)(e0 + lrow) * Dn + kb + lq * 4];
        Bs[lq * 4 + 0][lrow] = b4.x;
        Bs[lq * 4 + 1][lrow] = b4.y;
        Bs[lq * 4 + 2][lrow] = b4.z;
        Bs[lq * 4 + 3][lrow] = b4.w;
        __syncthreads();
#pragma unroll
        for (int kk = 0; kk < 16; kk++) {
            float a[4], b[4];
#pragma unroll
            for (int u = 0; u < 4; u++) a[u] = As[kk][ty * 4 + u];
#pragma unroll
            for (int u = 0; u < 4; u++) b[u] = Bs[kk][tx * 4 + u];
#pragma unroll
            for (int i = 0; i < 4; i++)
#pragma unroll
                for (int j = 0; j < 4; j++) acc[i][j] = fmaf(a[i], b[j], acc[i][j]);
        }
        __syncthreads();
    }

#pragma unroll
    for (int i = 0; i < 4; i++) {
        int m = m0 + ty * 4 + i;
#pragma unroll
        for (int j = 0; j < 4; j++) {
            int e = e0 + tx * 4 + j;
            out[(size_t)m * Dn + e] = acc[i][j];
        }
    }
}

// ---------------------------------------------------------------------------
// Tail: x_last output (x[:, T-1, :])
// ---------------------------------------------------------------------------
__global__ void tail_xlast(const float* __restrict__ x, float* __restrict__ out_x) {
    int i = blockIdx.x * blockDim.x + threadIdx.x;
    if (i < Bn * Dn) {
        int b = i / Dn;
        int d = i & (Dn - 1);
        out_x[i] = x[((size_t)b * Tn + (Tn - 1)) * Dn + d];
    }
}

// ---------------------------------------------------------------------------
// Launch
// ---------------------------------------------------------------------------
extern "C" void kernel_launch(void* const* d_in, const int* in_sizes, int n_in,
                              void* d_out, int out_size) {
    const float* x       = (const float*)d_in[0];
    const float* last_x  = (const float*)d_in[1];
    const float* last_num = (const float*)d_in[2];
    const float* last_den = (const float*)d_in[3];
    const float* td  = (const float*)d_in[4];   // time_decay
    const float* tf  = (const float*)d_in[5];   // time_first
    const float* tmk = (const float*)d_in[6];
    const float* tmv = (const float*)d_in[7];
    const float* tmr = (const float*)d_in[8];
    const float* Wk  = (const float*)d_in[9];
    const float* Wv  = (const float*)d_in[10];
    const float* Wr  = (const float*)d_in[11];
    const float* Wo  = (const float*)d_in[12];

    float* out      = (float*)d_out;                    // [M, D]
    float* out_x    = out + (size_t)Mn * Dn;            // [B, D]
    float* out_num  = out_x + Bn * Dn;                  // [B, D]
    float* out_den  = out_num + Bn * Dn;                // [B, D]

    prep_scale<<<(Dn * Dn / 4 + 255) / 256, 256>>>(Wk, Wv, Wr, tmk, tmv, tmr);
    prep_bias<<<Dn, 256>>>(Wk, Wv, Wr, last_x, tmk, tmv, tmr);

    dim3 grid(Dn / 64, Mn / 64);   // (16, 256)
    gemm_kvr<<<grid, 256>>>(x, tf, td, last_num, last_den, out_num, out_den);
    gemm_out<<<grid, 256>>>(Wo, out);

    tail_xlast<<<(Bn * Dn + 255) / 256, 256>>>(x, out_x);
}

// round 6
// speedup vs baseline: 2.3125x; 2.3125x over previous
#include <cuda_runtime.h>
#include <cuda_bf16.h>
#include <math.h>
#include <stdint.h>

// Problem constants (B=4, T=4096, D=1024)
#define Bn 4
#define Tn 4096
#define Dn 1024
#define Mn (Bn * Tn)          // 16384

typedef __nv_bfloat16 bf16;

// ---------------- device scratch (alloc-free rule: __device__ globals) -----
__device__ __align__(128) bf16 g_Wh[3][Dn * Dn];     // pre-scaled weights hi
__device__ __align__(128) bf16 g_Wl[3][Dn * Dn];     // lo
__device__ __align__(128) bf16 g_Woh[Dn * Dn];
__device__ __align__(128) bf16 g_Wol[Dn * Dn];
__device__ __align__(128) bf16 g_xh[(size_t)Mn * Dn];   // split of x
__device__ __align__(128) bf16 g_xl[(size_t)Mn * Dn];
__device__ __align__(128) bf16 g_ah[(size_t)Mn * Dn];   // split of rwkv
__device__ __align__(128) bf16 g_al[(size_t)Mn * Dn];
__device__ __align__(128) float g_kvr[3][(size_t)Mn * Dn]; // k,v,r pre-activation
__device__ float g_b[3 * Dn];                            // folded biases

// ---------------- helpers ----------------
__device__ __forceinline__ uint32_t smem_u32(const void* p) {
    uint32_t a;
    asm("{ .reg .u64 t; cvta.to.shared.u64 t, %1; cvt.u32.u64 %0, t; }" : "=r"(a) : "l"(p));
    return a;
}

__device__ __forceinline__ void split2(float v, uint16_t& h, uint16_t& l) {
    bf16 hb = __float2bfloat16_rn(v);
    float r = v - __bfloat162float(hb);
    bf16 lb = __float2bfloat16_rn(r);
    h = *(uint16_t*)&hb;
    l = *(uint16_t*)&lb;
}

__device__ __forceinline__ void cp16(uint32_t saddr, const void* g) {
    asm volatile("cp.async.cg.shared.global [%0], [%1], 16;" :: "r"(saddr), "l"(g));
}
#define CP_COMMIT() asm volatile("cp.async.commit_group;")
#define CP_WAIT1()  asm volatile("cp.async.wait_group 1;")

#define MMA16816(cc, a, b0v, b1v) \
    asm volatile("mma.sync.aligned.m16n8k16.row.col.f32.bf16.bf16.f32 " \
        "{%0,%1,%2,%3}, {%4,%5,%6,%7}, {%8,%9}, {%0,%1,%2,%3};" \
        : "+f"((cc)[0]), "+f"((cc)[1]), "+f"((cc)[2]), "+f"((cc)[3]) \
        : "r"((a)[0]), "r"((a)[1]), "r"((a)[2]), "r"((a)[3]), "r"(b0v), "r"(b1v))

// smem tile geometry: 128 rows x 32 bf16, padded row stride of 40 elems (80B)
// 80B stride -> ldmatrix 8-lane groups hit distinct banks (20r mod 32 distinct).
#define TSTR 40
#define TILE_E (128 * TSTR)      // elems per tile
#define STAGE_E (4 * TILE_E)     // Ah, Al, Bh, Bl
#define NCH 32                   // K chunks (1024/32)

// A fragment (m16n8k16 row): ldmatrix.x4 -> 4 regs
__device__ __forceinline__ void lda4(uint32_t* r, const bf16* tile, int row0, int k0, int lane) {
    int row = row0 + (lane & 15);
    int col = k0 + ((lane & 16) >> 1);   // lanes 16-31 read k+8 half
    uint32_t a = smem_u32(tile + row * TSTR + col);
    asm volatile("ldmatrix.sync.aligned.m8n8.x4.shared.b16 {%0,%1,%2,%3}, [%4];"
        : "=r"(r[0]), "=r"(r[1]), "=r"(r[2]), "=r"(r[3]) : "r"(a));
}
// B fragments for two adjacent n8 tiles: ldmatrix.x4 -> {n0 reg0, n0 reg1, n1 reg0, n1 reg1}
__device__ __forceinline__ void ldb4(uint32_t* r, const bf16* tile, int row0, int k0, int lane) {
    int row = row0 + (lane & 7) + ((lane & 16) >> 1);
    int col = k0 + (lane & 8);
    uint32_t a = smem_u32(tile + row * TSTR + col);
    asm volatile("ldmatrix.sync.aligned.m8n8.x4.shared.b16 {%0,%1,%2,%3}, [%4];"
        : "=r"(r[0]), "=r"(r[1]), "=r"(r[2]), "=r"(r[3]) : "r"(a));
}

// ---------------- prep kernels ----------------
// split plain fp32 -> bf16 hi/lo (x, Wo)
__global__ void prep_split(const float* __restrict__ src, bf16* __restrict__ dh,
                           bf16* __restrict__ dl, int n4) {
    int i = blockIdx.x * blockDim.x + threadIdx.x;
    if (i >= n4) return;
    float4 v = ((const float4*)src)[i];
    float vv[4] = {v.x, v.y, v.z, v.w};
    uint16_t h[4], l[4];
#pragma unroll
    for (int q = 0; q < 4; q++) split2(vv[q], h[q], l[q]);
    ((uint2*)dh)[i] = make_uint2((uint32_t)h[0] | ((uint32_t)h[1] << 16),
                                 (uint32_t)h[2] | ((uint32_t)h[3] << 16));
    ((uint2*)dl)[i] = make_uint2((uint32_t)l[0] | ((uint32_t)l[1] << 16),
                                 (uint32_t)l[2] | ((uint32_t)l[3] << 16));
}

// scale Wk/Wv/Wr columns by time-mix, then split
__global__ void prep_w(const float* __restrict__ Wk, const float* __restrict__ Wv,
                       const float* __restrict__ Wr, const float* __restrict__ tmk,
                       const float* __restrict__ tmv, const float* __restrict__ tmr) {
    int idx = blockIdx.x * blockDim.x + threadIdx.x;
    if (idx >= Dn * Dn / 4) return;
    int basei = idx * 4;
    int d = basei & (Dn - 1);
    const float* Ws[3] = {Wk, Wv, Wr};
    const float* Tm[3] = {tmk, tmv, tmr};
#pragma unroll
    for (int i = 0; i < 3; i++) {
        float4 w = *(const float4*)&Ws[i][basei];
        float4 mm = *(const float4*)&Tm[i][d];
        float vv[4] = {w.x * mm.x, w.y * mm.y, w.z * mm.z, w.w * mm.w};
        uint16_t h[4], l[4];
#pragma unroll
        for (int q = 0; q < 4; q++) split2(vv[q], h[q], l[q]);
        *(uint2*)&g_Wh[i][basei] = make_uint2((uint32_t)h[0] | ((uint32_t)h[1] << 16),
                                              (uint32_t)h[2] | ((uint32_t)h[3] << 16));
        *(uint2*)&g_Wl[i][basei] = make_uint2((uint32_t)l[0] | ((uint32_t)l[1] << 16),
                                              (uint32_t)l[2] | ((uint32_t)l[3] << 16));
    }
}

__global__ void prep_bias(const float* __restrict__ Wk, const float* __restrict__ Wv,
                          const float* __restrict__ Wr, const float* __restrict__ lx,
                          const float* __restrict__ tmk, const float* __restrict__ tmv,
                          const float* __restrict__ tmr) {
    __shared__ float red[256];
    int e = blockIdx.x;
    int t = threadIdx.x;
    const float* Ws[3] = {Wk, Wv, Wr};
    const float* tms[3] = {tmk, tmv, tmr};
#pragma unroll
    for (int i = 0; i < 3; i++) {
        float s = 0.f;
        for (int d = t; d < Dn; d += 256)
            s += Ws[i][(size_t)e * Dn + d] * lx[d] * (1.f - tms[i][d]);
        red[t] = s;
        __syncthreads();
        for (int off = 128; off > 0; off >>= 1) {
            if (t < off) red[t] += red[t + off];
            __syncthreads();
        }
        if (t == 0) g_b[i * Dn + e] = red[0];
        __syncthreads();
    }
}

// ---------------- generic bf16x3 GEMM: C[m][n] = sum_k A[m][k] * B[n][k] ----
// mode 0: A = x split, B = W[z] split, C = g_kvr[z]   (grid.z = 3)
// mode 1: A = rwkv split, B = Wo split, C = outp      (grid.z = 1)
__global__ __launch_bounds__(256, 1)
void gemm_bf16x3(int mode, float* __restrict__ outp) {
    extern __shared__ bf16 sm[];
    const int t = threadIdx.x;
    const int lane = t & 31, wid = t >> 5;
    const int e0 = blockIdx.x * 128, m0 = blockIdx.y * 128;
    const int z = blockIdx.z;

    const bf16 *Ah, *Al, *Bh, *Bl;
    float* C;
    if (mode == 0) { Ah = g_xh; Al = g_xl; Bh = g_Wh[z]; Bl = g_Wl[z]; C = g_kvr[z]; }
    else           { Ah = g_ah; Al = g_al; Bh = g_Woh;   Bl = g_Wol;   C = outp; }

    uint32_t sbase = smem_u32(sm);

    auto stage_load = [&](int ch, int stg) {
        uint32_t s0 = sbase + stg * STAGE_E * 2;
        int kcol = ch * 32;
#pragma unroll
        for (int i = 0; i < 2; i++) {
            int idx = t + i * 256;
            int row = idx >> 2, q = idx & 3;
            uint32_t soff = (uint32_t)(row * TSTR + q * 8) * 2;
            size_t goffA = (size_t)(m0 + row) * Dn + kcol + q * 8;
            size_t goffB = (size_t)(e0 + row) * Dn + kcol + q * 8;
            cp16(s0 + soff,                Ah + goffA);
            cp16(s0 + TILE_E * 2 + soff,   Al + goffA);
            cp16(s0 + TILE_E * 4 + soff,   Bh + goffB);
            cp16(s0 + TILE_E * 6 + soff,   Bl + goffB);
        }
    };

    float c[4][4][4];
#pragma unroll
    for (int i = 0; i < 4; i++)
#pragma unroll
        for (int j = 0; j < 4; j++)
#pragma unroll
            for (int q = 0; q < 4; q++) c[i][j][q] = 0.f;

    stage_load(0, 0); CP_COMMIT();
    stage_load(1, 1); CP_COMMIT();

    const int mw = (wid >> 2) * 64;   // warp m offset within the 128-tile
    const int nw = (wid & 3) * 32;    // warp n offset

    for (int ch = 0; ch < NCH; ch++) {
        CP_WAIT1();
        __syncthreads();
        const bf16* st  = sm + (ch & 1) * STAGE_E;
        const bf16* tAh = st;
        const bf16* tAl = st + TILE_E;
        const bf16* tBh = st + 2 * TILE_E;
        const bf16* tBl = st + 3 * TILE_E;
#pragma unroll
        for (int s = 0; s < 2; s++) {
            int k0 = s * 16;
            uint32_t ah[4][4], al[4][4], bh[2][4], bl[2][4];
#pragma unroll
            for (int i = 0; i < 4; i++) {
                lda4(ah[i], tAh, mw + i * 16, k0, lane);
                lda4(al[i], tAl, mw + i * 16, k0, lane);
            }
#pragma unroll
            for (int jj = 0; jj < 2; jj++) {
                ldb4(bh[jj], tBh, nw + jj * 16, k0, lane);
                ldb4(bl[jj], tBl, nw + jj * 16, k0, lane);
            }
#pragma unroll
            for (int i = 0; i < 4; i++)
#pragma unroll
                for (int j = 0; j < 4; j++) {
                    uint32_t hb0 = bh[j >> 1][(j & 1) * 2], hb1 = bh[j >> 1][(j & 1) * 2 + 1];
                    uint32_t lb0 = bl[j >> 1][(j & 1) * 2], lb1 = bl[j >> 1][(j & 1) * 2 + 1];
                    MMA16816(c[i][j], ah[i], hb0, hb1);   // hi * hi
                    MMA16816(c[i][j], al[i], hb0, hb1);   // lo * hi
                    MMA16816(c[i][j], ah[i], lb0, lb1);   // hi * lo
                }
        }
        __syncthreads();
        if (ch + 2 < NCH) stage_load(ch + 2, ch & 1);
        CP_COMMIT();
    }

    // epilogue: write fp32 C
#pragma unroll
    for (int i = 0; i < 4; i++) {
        int mrow = m0 + mw + i * 16 + (lane >> 2);
#pragma unroll
        for (int j = 0; j < 4; j++) {
            int ncol = e0 + nw + j * 8 + (lane & 3) * 2;
            *(float2*)&C[(size_t)mrow * Dn + ncol] = make_float2(c[i][j][0], c[i][j][1]);
            *(float2*)&C[(size_t)(mrow + 8) * Dn + ncol] = make_float2(c[i][j][2], c[i][j][3]);
        }
    }
}

// ---------------- WKV elementwise epilogue ----------------
// reads k,v,r pre-activations, applies biases + WKV numerics,
// writes rwkv as bf16 hi/lo split, plus last-token num/den states.
__global__ void wkv_ep(const float* __restrict__ tf, const float* __restrict__ td,
                       const float* __restrict__ lnum, const float* __restrict__ lden,
                       float* __restrict__ out_num, float* __restrict__ out_den) {
    int i = blockIdx.x * blockDim.x + threadIdx.x;     // over Mn*Dn/4
    if (i >= Mn * Dn / 4) return;
    int m = i >> 8;                 // Dn/4 = 256 float4 per row
    int e = (i & 255) * 4;
    size_t off = (size_t)m * Dn + e;
    float4 k4 = *(const float4*)&g_kvr[0][off];
    float4 v4 = *(const float4*)&g_kvr[1][off];
    float4 r4 = *(const float4*)&g_kvr[2][off];
    float kk[4] = {k4.x, k4.y, k4.z, k4.w};
    float vv[4] = {v4.x, v4.y, v4.z, v4.w};
    float rr[4] = {r4.x, r4.y, r4.z, r4.w};
    const bool last = ((m & (Tn - 1)) == (Tn - 1));
    const int bidx = m >> 12;
    uint16_t h[4], l[4];
#pragma unroll
    for (int q = 0; q < 4; q++) {
        int eq = e + q;
        float kv = kk[q] + g_b[eq];
        float vvq = vv[q] + g_b[Dn + eq];
        float rv = rr[q] + g_b[2 * Dn + eq];
        float efk = expf(tf[eq] + kv);
        float wkv = (lnum[eq] + efk * vvq) / (lden[eq] + efk);
        float val = wkv / (1.f + expf(-rv));
        split2(val, h[q], l[q]);
        if (last) {
            float ek = expf(kv);
            float dec = expf(-expf(td[eq]));
            out_num[bidx * Dn + eq] = dec * lnum[eq] + ek * vvq;
            out_den[bidx * Dn + eq] = dec * lden[eq] + ek;
        }
    }
    ((uint2*)g_ah)[i] = make_uint2((uint32_t)h[0] | ((uint32_t)h[1] << 16),
                                   (uint32_t)h[2] | ((uint32_t)h[3] << 16));
    ((uint2*)g_al)[i] = make_uint2((uint32_t)l[0] | ((uint32_t)l[1] << 16),
                                   (uint32_t)l[2] | ((uint32_t)l[3] << 16));
}

// ---------------- tail ----------------
__global__ void tail_xlast(const float* __restrict__ x, float* __restrict__ out_x) {
    int i = blockIdx.x * blockDim.x + threadIdx.x;
    if (i < Bn * Dn) {
        int b = i / Dn;
        int d = i & (Dn - 1);
        out_x[i] = x[((size_t)b * Tn + (Tn - 1)) * Dn + d];
    }
}

// ---------------- launch ----------------
extern "C" void kernel_launch(void* const* d_in, const int* in_sizes, int n_in,
                              void* d_out, int out_size) {
    const float* x        = (const float*)d_in[0];
    const float* last_x   = (const float*)d_in[1];
    const float* last_num = (const float*)d_in[2];
    const float* last_den = (const float*)d_in[3];
    const float* td  = (const float*)d_in[4];
    const float* tf  = (const float*)d_in[5];
    const float* tmk = (const float*)d_in[6];
    const float* tmv = (const float*)d_in[7];
    const float* tmr = (const float*)d_in[8];
    const float* Wk  = (const float*)d_in[9];
    const float* Wv  = (const float*)d_in[10];
    const float* Wr  = (const float*)d_in[11];
    const float* Wo  = (const float*)d_in[12];

    float* out     = (float*)d_out;
    float* out_x   = out + (size_t)Mn * Dn;
    float* out_num = out_x + Bn * Dn;
    float* out_den = out_num + Bn * Dn;

    const int GEMM_SMEM = 2 * STAGE_E * 2;   // 81920 bytes
    cudaFuncSetAttribute(gemm_bf16x3, cudaFuncAttributeMaxDynamicSharedMemorySize, GEMM_SMEM);

    // resolve split destinations for x / Wo via symbol pointers
    bf16 *p_xh, *p_xl, *p_woh, *p_wol;
    cudaGetSymbolAddress((void**)&p_xh, g_xh);
    cudaGetSymbolAddress((void**)&p_xl, g_xl);
    cudaGetSymbolAddress((void**)&p_woh, g_Woh);
    cudaGetSymbolAddress((void**)&p_wol, g_Wol);

    // prep
    prep_w<<<(Dn * Dn / 4 + 255) / 256, 256>>>(Wk, Wv, Wr, tmk, tmv, tmr);
    prep_split<<<(Dn * Dn / 4 + 255) / 256, 256>>>(Wo, p_woh, p_wol, Dn * Dn / 4);
    prep_split<<<(Mn * Dn / 4 + 255) / 256, 256>>>(x, p_xh, p_xl, Mn * Dn / 4);
    prep_bias<<<Dn, 256>>>(Wk, Wv, Wr, last_x, tmk, tmv, tmr);

    // k, v, r GEMMs (z = 0..2)
    dim3 grid_kvr(Dn / 128, Mn / 128, 3);
    gemm_bf16x3<<<grid_kvr, 256, GEMM_SMEM>>>(0, nullptr);

    // WKV elementwise + rwkv split
    wkv_ep<<<(Mn * Dn / 4 + 255) / 256, 256>>>(tf, td, last_num, last_den, out_num, out_den);

    // output GEMM
    dim3 grid_out(Dn / 128, Mn / 128, 1);
    gemm_bf16x3<<<grid_out, 256, GEMM_SMEM>>>(1, out);

    tail_xlast<<<(Bn * Dn + 255) / 256, 256>>>(x, out_x);
}